// round 7
// baseline (speedup 1.0000x reference)
#include <cuda_runtime.h>
#include <math.h>
#include <stdint.h>

#define NN 50000
#define EE 800000
#define ETOT (EE + NN)

// ---------------- device scratch ----------------
__device__ __align__(16) float g_h[NN * 64];     // pre-attention features
__device__ __align__(16) float g_feat[NN * 64];  // layer output -> next input
__device__ __align__(16) float g_as[NN * 4];     // alpha_src per (node, head)
__device__ __align__(16) float g_ad[NN * 4];     // alpha_dst per (node, head)
__device__ int g_deg[NN];         // in-degree histogram
__device__ int g_rowptr[NN + 1];  // CSR row pointers
__device__ int g_cursor[NN];      // fill cursors
__device__ int g_csr[ETOT];       // CSR src indices (incl. self loops)

// ---------------- packed f32x2 helpers ----------------
__device__ __forceinline__ void ffma2(unsigned long long& acc, unsigned long long a,
                                      unsigned long long b) {
    asm("fma.rn.f32x2 %0, %1, %2, %0;" : "+l"(acc) : "l"(a), "l"(b));
}
__device__ __forceinline__ unsigned long long bcast2(float x) {
    unsigned long long r;
    asm("mov.b64 %0, {%1, %1};" : "=l"(r) : "f"(x));
    return r;
}
__device__ __forceinline__ float2 unpack2(unsigned long long p) {
    float2 f;
    asm("mov.b64 {%0, %1}, %2;" : "=f"(f.x), "=f"(f.y) : "l"(p));
    return f;
}

// ---------------- GEMM: C[n, FOUT] = X[n, FIN] * W[FIN, FOUT] ----------------
// TM=64 rows/block, 2 rows x 4 cols per thread, blockDim = CG*32, minBlocks=2.
// If ALPHA: fused attention-logit epilogue (FOUT=64, H=4, C=16, CG=16).
template <int FIN, int FOUT, int TK, bool ALPHA>
__global__ void __launch_bounds__((FOUT / 4) * 32, 2) gemm_kernel(
    const float* __restrict__ X, const float* __restrict__ W,
    float* __restrict__ C, const float* __restrict__ asrc,
    const float* __restrict__ adst, int nrows) {
    constexpr int CG = FOUT / 4;
    constexpr int TM = 64;
    constexpr int XPITCH = TK + 4;
    constexpr int NT = CG * 32;
    extern __shared__ float smem[];
    float* Xs = smem;                   // TM * XPITCH
    float* Ws = smem + TM * XPITCH;     // TK * FOUT

    const int tid = threadIdx.x;
    const int cg = tid % CG;
    const int rg = tid / CG;            // 0..31
    const int rowBase = blockIdx.x * TM;

    float a_s[4], a_d[4];
    if (ALPHA) {
#pragma unroll
        for (int j = 0; j < 4; j++) {
            a_s[j] = __ldg(asrc + cg * 4 + j);
            a_d[j] = __ldg(adst + cg * 4 + j);
        }
    }

    unsigned long long acc01[2], acc23[2];
#pragma unroll
    for (int i = 0; i < 2; i++) { acc01[i] = 0ull; acc23[i] = 0ull; }

    for (int k0 = 0; k0 < FIN; k0 += TK) {
        __syncthreads();
        for (int idx = tid; idx < TM * (TK / 4); idx += NT) {
            int r = idx / (TK / 4);
            int k4 = idx % (TK / 4);
            float4 v = make_float4(0.f, 0.f, 0.f, 0.f);
            int row = rowBase + r;
            if (row < nrows)
                v = *(const float4*)(X + (size_t)row * FIN + k0 + k4 * 4);
            *(float4*)(Xs + r * XPITCH + k4 * 4) = v;
        }
        for (int idx = tid; idx < TK * CG; idx += NT) {
            int k = idx / CG;
            int c4 = idx % CG;
            *(float4*)(Ws + k * FOUT + c4 * 4) =
                *(const float4*)(W + (size_t)(k0 + k) * FOUT + c4 * 4);
        }
        __syncthreads();

#pragma unroll 4
        for (int k4 = 0; k4 < TK / 4; k4++) {
            float4 xq[2];
#pragma unroll
            for (int i = 0; i < 2; i++)
                xq[i] = *(float4*)(Xs + (rg * 2 + i) * XPITCH + k4 * 4);
#pragma unroll
            for (int kk = 0; kk < 4; kk++) {
                ulonglong2 wv = *(const ulonglong2*)(Ws + (k4 * 4 + kk) * FOUT + cg * 4);
#pragma unroll
                for (int i = 0; i < 2; i++) {
                    float xv = (kk == 0) ? xq[i].x : (kk == 1) ? xq[i].y
                              : (kk == 2) ? xq[i].z : xq[i].w;
                    unsigned long long x2 = bcast2(xv);
                    ffma2(acc01[i], x2, wv.x);
                    ffma2(acc23[i], x2, wv.y);
                }
            }
        }
    }

#pragma unroll
    for (int i = 0; i < 2; i++) {
        int row = rowBase + rg * 2 + i;
        float2 lo = unpack2(acc01[i]);
        float2 hi = unpack2(acc23[i]);
        float4 v = make_float4(lo.x, lo.y, hi.x, hi.y);
        if (row < nrows)
            *(float4*)(C + (size_t)row * FOUT + cg * 4) = v;
        if (ALPHA) {
            float p1 = v.x * a_s[0] + v.y * a_s[1] + v.z * a_s[2] + v.w * a_s[3];
            float p2 = v.x * a_d[0] + v.y * a_d[1] + v.z * a_d[2] + v.w * a_d[3];
            p1 += __shfl_xor_sync(0xffffffffu, p1, 1);
            p1 += __shfl_xor_sync(0xffffffffu, p1, 2);
            p2 += __shfl_xor_sync(0xffffffffu, p2, 1);
            p2 += __shfl_xor_sync(0xffffffffu, p2, 2);
            if ((cg & 3) == 0 && row < nrows) {
                g_as[row * 4 + (cg >> 2)] = p1;
                g_ad[row * 4 + (cg >> 2)] = p2;
            }
        }
    }
}

// ---------------- CSR construction ----------------
__global__ void hist_kernel(const int* __restrict__ dsts) {
    int e = blockIdx.x * blockDim.x + threadIdx.x;
    if (e >= ETOT) return;
    int d = (e < EE) ? __ldg(dsts + e) : (e - EE);
    atomicAdd(&g_deg[d], 1);
}

__global__ void scan_kernel() {
    __shared__ int sums[1024];
    const int t = threadIdx.x;
    constexpr int CH = (NN + 1 + 1023) / 1024;
    const int base = t * CH;
    int s = 0;
    for (int j = 0; j < CH; j++) {
        int idx = base + j;
        if (idx < NN) s += g_deg[idx];
    }
    sums[t] = s;
    __syncthreads();
    for (int off = 1; off < 1024; off <<= 1) {
        int v = (t >= off) ? sums[t - off] : 0;
        __syncthreads();
        sums[t] += v;
        __syncthreads();
    }
    int run = (t == 0) ? 0 : sums[t - 1];
    for (int j = 0; j < CH; j++) {
        int idx = base + j;
        if (idx <= NN) {
            g_rowptr[idx] = run;
            if (idx < NN) {
                g_cursor[idx] = run;
                run += g_deg[idx];
            }
        }
    }
}

__global__ void fill_kernel(const int* __restrict__ srcs, const int* __restrict__ dsts) {
    int e = blockIdx.x * blockDim.x + threadIdx.x;
    if (e >= ETOT) return;
    int s, d;
    if (e < EE) { s = __ldg(srcs + e); d = __ldg(dsts + e); }
    else        { s = d = e - EE; }
    int pos = atomicAdd(&g_cursor[d], 1);
    g_csr[pos] = s;
}

// ---------------- prep (layer 3 only): attention logits ----------------
template <int H, int C>
__global__ void prep_kernel(const float* __restrict__ h,
                            const float* __restrict__ a_src,
                            const float* __restrict__ a_dst) {
    int t = blockIdx.x * blockDim.x + threadIdx.x;
    if (t >= NN * H) return;
    int n = t / H, hh = t % H;
    const float* hp = h + (size_t)n * (H * C) + hh * C;
    const float* sv = a_src + hh * C;
    const float* dv = a_dst + hh * C;
    float s1 = 0.f, s2 = 0.f;
#pragma unroll
    for (int c = 0; c < C; c++) {
        float v = hp[c];
        s1 += v * sv[c];
        s2 += v * dv[c];
    }
    g_as[t] = s1;
    g_ad[t] = s2;
}

// ---------------- aggregate: gather-side softmax-weighted sum + bias (+relu) ----------------
template <int H, int C, bool RELU>
__global__ void aggregate_kernel(const float* __restrict__ h,
                                 const float* __restrict__ bias,
                                 float* __restrict__ dest) {
    constexpr int F = H * C;
    constexpr int NV = F / 4;
    int gt = blockIdx.x * blockDim.x + threadIdx.x;
    int n = gt >> 4;
    int q = gt & 15;
    if (n >= NN) return;
    int hh = (H == 1) ? 0 : (q >> 2);

    const float ad = g_ad[n * H + hh];
    const int beg = __ldg(g_rowptr + n);
    const int end = __ldg(g_rowptr + n + 1);

    float4 acc = make_float4(0.f, 0.f, 0.f, 0.f);
    float den = 0.f;
    for (int i = beg; i < end; i++) {
        int s = __ldg(g_csr + i);
        float v = __ldg(g_as + s * H + hh) + ad;
        v = v > 0.f ? v : 0.2f * v;
        float w = __expf(v);
        den += w;
        if (q < NV) {
            float4 x = __ldg((const float4*)(h + (size_t)s * F) + q);
            acc.x += w * x.x;
            acc.y += w * x.y;
            acc.z += w * x.z;
            acc.w += w * x.w;
        }
    }
    if (q < NV) {
        float inv = 1.f / (den + 1e-16f);
        float4 b = __ldg((const float4*)bias + q);
        float4 o;
        o.x = acc.x * inv + b.x;
        o.y = acc.y * inv + b.y;
        o.z = acc.z * inv + b.z;
        o.w = acc.w * inv + b.w;
        if (RELU) {
            o.x = o.x > 0.f ? o.x : 0.f;
            o.y = o.y > 0.f ? o.y : 0.f;
            o.z = o.z > 0.f ? o.z : 0.f;
            o.w = o.w > 0.f ? o.w : 0.f;
        }
        *(float4*)(dest + (size_t)n * F + q * 4) = o;
    }
}

// ---------------- launch ----------------
extern "C" void kernel_launch(void* const* d_in, const int* in_sizes, int n_in,
                              void* d_out, int out_size) {
    const float* x = (const float*)d_in[0];
    const int* ei = (const int*)d_in[1];    // int32 (JAX x64 disabled)
    const float* W1 = (const float*)d_in[2];
    const float* asr1 = (const float*)d_in[3];
    const float* adr1 = (const float*)d_in[4];
    const float* b1 = (const float*)d_in[5];
    const float* W2 = (const float*)d_in[6];
    const float* asr2 = (const float*)d_in[7];
    const float* adr2 = (const float*)d_in[8];
    const float* b2 = (const float*)d_in[9];
    const float* W3 = (const float*)d_in[10];
    const float* asr3 = (const float*)d_in[11];
    const float* adr3 = (const float*)d_in[12];
    const float* b3 = (const float*)d_in[13];
    float* out = (float*)d_out;

    const int* esrc = ei;
    const int* edst = ei + EE;

    float *p_h, *p_feat;
    void* p_deg;
    cudaGetSymbolAddress((void**)&p_h, g_h);
    cudaGetSymbolAddress((void**)&p_feat, g_feat);
    cudaGetSymbolAddress(&p_deg, g_deg);

    constexpr int SMEM64 = (64 * (64 + 4) + 64 * 64) * 4;  // 33792
    constexpr int SMEM40 = (64 * (64 + 4) + 64 * 40) * 4;  // 27648

    const int gemmGrid = (NN + 63) / 64;   // 782
    const int edgeGrid = (ETOT + 255) / 256;
    const int aggGrid = (NN * 16 + 255) / 256;

    // Fork: CSR build on a side stream, overlapped with layer-1 GEMM.
    // kernel_launch runs only twice (correctness + capture); replays use the graph,
    // so per-call stream/event creation costs nothing in the timed loop.
    cudaStream_t s2;
    cudaStreamCreateWithFlags(&s2, cudaStreamNonBlocking);
    cudaEvent_t evFork, evJoin;
    cudaEventCreateWithFlags(&evFork, cudaEventDisableTiming);
    cudaEventCreateWithFlags(&evJoin, cudaEventDisableTiming);

    cudaEventRecord(evFork, 0);
    cudaStreamWaitEvent(s2, evFork, 0);
    cudaMemsetAsync(p_deg, 0, NN * sizeof(int), s2);
    hist_kernel<<<edgeGrid, 256, 0, s2>>>(edst);
    scan_kernel<<<1, 1024, 0, s2>>>();
    fill_kernel<<<edgeGrid, 256, 0, s2>>>(esrc, edst);
    cudaEventRecord(evJoin, s2);

    // ---------------- layer 1: 256 -> 4x16 ----------------
    gemm_kernel<256, 64, 64, true><<<gemmGrid, 512, SMEM64>>>(x, W1, p_h, asr1, adr1, NN);
    cudaStreamWaitEvent(0, evJoin, 0);   // CSR must be ready before aggregation
    aggregate_kernel<4, 16, true><<<aggGrid, 256>>>(p_h, b1, p_feat);

    // ---------------- layer 2: 64 -> 4x16 ----------------
    gemm_kernel<64, 64, 64, true><<<gemmGrid, 512, SMEM64>>>(p_feat, W2, p_h, asr2, adr2, NN);
    aggregate_kernel<4, 16, true><<<aggGrid, 256>>>(p_h, b2, p_feat);

    // ---------------- layer 3: 64 -> 1x40 ----------------
    gemm_kernel<64, 40, 64, false><<<gemmGrid, 320, SMEM40>>>(p_feat, W3, p_h, nullptr, nullptr, NN);
    prep_kernel<1, 40><<<(NN + 255) / 256, 256>>>(p_h, asr3, adr3);
    aggregate_kernel<1, 40, false><<<aggGrid, 256>>>(p_h, b3, out);
}

// round 8
// speedup vs baseline: 1.5199x; 1.5199x over previous
#include <cuda_runtime.h>
#include <math.h>
#include <stdint.h>

#define NN 50000
#define EE 800000
#define ETOT (EE + NN)

// ---------------- device scratch ----------------
__device__ __align__(16) float g_h[NN * 64];     // pre-attention features
__device__ __align__(16) float g_feat[NN * 64];  // layer output -> next input
__device__ __align__(16) float g_as[NN * 4];     // alpha_src per (node, head)
__device__ __align__(16) float g_ad[NN * 4];     // alpha_dst per (node, head)
__device__ int g_deg[NN];         // in-degree histogram
__device__ int g_rowptr[NN + 1];  // CSR row pointers
__device__ int g_cursor[NN];      // fill cursors
__device__ int g_csr[ETOT];       // CSR src indices (incl. self loops)

// ---------------- packed f32x2 helpers ----------------
__device__ __forceinline__ void ffma2(unsigned long long& acc, unsigned long long a,
                                      unsigned long long b) {
    asm("fma.rn.f32x2 %0, %1, %2, %0;" : "+l"(acc) : "l"(a), "l"(b));
}
__device__ __forceinline__ unsigned long long bcast2(float x) {
    unsigned long long r;
    asm("mov.b64 %0, {%1, %1};" : "=l"(r) : "f"(x));
    return r;
}
__device__ __forceinline__ float2 unpack2(unsigned long long p) {
    float2 f;
    asm("mov.b64 {%0, %1}, %2;" : "=f"(f.x), "=f"(f.y) : "l"(p));
    return f;
}

// ---------------- GEMM: C[n, FOUT] = X[n, FIN] * W[FIN, FOUT] ----------------
// TM=64 rows/block, 4 rows x 4 cols per thread, blockDim = CG*16, minBlocks=3.
// If ALPHA: fused attention-logit epilogue (FOUT=64, H=4, C=16, CG=16).
template <int FIN, int FOUT, int TK, bool ALPHA>
__global__ void __launch_bounds__((FOUT / 4) * 16, 3) gemm_kernel(
    const float* __restrict__ X, const float* __restrict__ W,
    float* __restrict__ C, const float* __restrict__ asrc,
    const float* __restrict__ adst, int nrows) {
    constexpr int CG = FOUT / 4;
    constexpr int TM = 64;
    constexpr int XPITCH = TK + 4;
    constexpr int NT = CG * 16;
    extern __shared__ float smem[];
    float* Xs = smem;                   // TM * XPITCH
    float* Ws = smem + TM * XPITCH;     // TK * FOUT

    const int tid = threadIdx.x;
    const int cg = tid % CG;
    const int rg = tid / CG;            // 0..15
    const int rowBase = blockIdx.x * TM;

    float a_s[4], a_d[4];
    if (ALPHA) {
#pragma unroll
        for (int j = 0; j < 4; j++) {
            a_s[j] = __ldg(asrc + cg * 4 + j);
            a_d[j] = __ldg(adst + cg * 4 + j);
        }
    }

    unsigned long long acc01[4], acc23[4];
#pragma unroll
    for (int i = 0; i < 4; i++) { acc01[i] = 0ull; acc23[i] = 0ull; }

    for (int k0 = 0; k0 < FIN; k0 += TK) {
        __syncthreads();
        for (int idx = tid; idx < TM * (TK / 4); idx += NT) {
            int r = idx / (TK / 4);
            int k4 = idx % (TK / 4);
            float4 v = make_float4(0.f, 0.f, 0.f, 0.f);
            int row = rowBase + r;
            if (row < nrows)
                v = *(const float4*)(X + (size_t)row * FIN + k0 + k4 * 4);
            *(float4*)(Xs + r * XPITCH + k4 * 4) = v;
        }
        for (int idx = tid; idx < TK * CG; idx += NT) {
            int k = idx / CG;
            int c4 = idx % CG;
            *(float4*)(Ws + k * FOUT + c4 * 4) =
                *(const float4*)(W + (size_t)(k0 + k) * FOUT + c4 * 4);
        }
        __syncthreads();

        for (int k4 = 0; k4 < TK / 4; k4++) {
            float4 xq[4];
#pragma unroll
            for (int i = 0; i < 4; i++)
                xq[i] = *(float4*)(Xs + (rg * 4 + i) * XPITCH + k4 * 4);
#pragma unroll
            for (int kk = 0; kk < 4; kk++) {
                ulonglong2 wv = *(const ulonglong2*)(Ws + (k4 * 4 + kk) * FOUT + cg * 4);
#pragma unroll
                for (int i = 0; i < 4; i++) {
                    float xv = (kk == 0) ? xq[i].x : (kk == 1) ? xq[i].y
                              : (kk == 2) ? xq[i].z : xq[i].w;
                    unsigned long long x2 = bcast2(xv);
                    ffma2(acc01[i], x2, wv.x);
                    ffma2(acc23[i], x2, wv.y);
                }
            }
        }
    }

#pragma unroll
    for (int i = 0; i < 4; i++) {
        int row = rowBase + rg * 4 + i;
        float2 lo = unpack2(acc01[i]);
        float2 hi = unpack2(acc23[i]);
        float4 v = make_float4(lo.x, lo.y, hi.x, hi.y);
        if (row < nrows)
            *(float4*)(C + (size_t)row * FOUT + cg * 4) = v;
        if (ALPHA) {
            float p1 = v.x * a_s[0] + v.y * a_s[1] + v.z * a_s[2] + v.w * a_s[3];
            float p2 = v.x * a_d[0] + v.y * a_d[1] + v.z * a_d[2] + v.w * a_d[3];
            p1 += __shfl_xor_sync(0xffffffffu, p1, 1);
            p1 += __shfl_xor_sync(0xffffffffu, p1, 2);
            p2 += __shfl_xor_sync(0xffffffffu, p2, 1);
            p2 += __shfl_xor_sync(0xffffffffu, p2, 2);
            if ((cg & 3) == 0 && row < nrows) {
                g_as[row * 4 + (cg >> 2)] = p1;
                g_ad[row * 4 + (cg >> 2)] = p2;
            }
        }
    }
}

// ---------------- CSR construction ----------------
__global__ void hist_kernel(const int* __restrict__ dsts) {
    int e = blockIdx.x * blockDim.x + threadIdx.x;
    if (e >= ETOT) return;
    int d = (e < EE) ? __ldg(dsts + e) : (e - EE);
    atomicAdd(&g_deg[d], 1);
}

__global__ void scan_kernel() {
    __shared__ int sums[1024];
    const int t = threadIdx.x;
    constexpr int CH = (NN + 1 + 1023) / 1024;
    const int base = t * CH;
    int s = 0;
    for (int j = 0; j < CH; j++) {
        int idx = base + j;
        if (idx < NN) s += g_deg[idx];
    }
    sums[t] = s;
    __syncthreads();
    for (int off = 1; off < 1024; off <<= 1) {
        int v = (t >= off) ? sums[t - off] : 0;
        __syncthreads();
        sums[t] += v;
        __syncthreads();
    }
    int run = (t == 0) ? 0 : sums[t - 1];
    for (int j = 0; j < CH; j++) {
        int idx = base + j;
        if (idx <= NN) {
            g_rowptr[idx] = run;
            if (idx < NN) {
                g_cursor[idx] = run;
                run += g_deg[idx];
            }
        }
    }
}

__global__ void fill_kernel(const int* __restrict__ srcs, const int* __restrict__ dsts) {
    int e = blockIdx.x * blockDim.x + threadIdx.x;
    if (e >= ETOT) return;
    int s, d;
    if (e < EE) { s = __ldg(srcs + e); d = __ldg(dsts + e); }
    else        { s = d = e - EE; }
    int pos = atomicAdd(&g_cursor[d], 1);
    g_csr[pos] = s;
}

// ---------------- prep (layer 3 only): attention logits ----------------
template <int H, int C>
__global__ void prep_kernel(const float* __restrict__ h,
                            const float* __restrict__ a_src,
                            const float* __restrict__ a_dst) {
    int t = blockIdx.x * blockDim.x + threadIdx.x;
    if (t >= NN * H) return;
    int n = t / H, hh = t % H;
    const float* hp = h + (size_t)n * (H * C) + hh * C;
    const float* sv = a_src + hh * C;
    const float* dv = a_dst + hh * C;
    float s1 = 0.f, s2 = 0.f;
#pragma unroll
    for (int c = 0; c < C; c++) {
        float v = hp[c];
        s1 += v * sv[c];
        s2 += v * dv[c];
    }
    g_as[t] = s1;
    g_ad[t] = s2;
}

// ---------------- aggregate: gather-side softmax-weighted sum + bias (+relu) ----------------
template <int H, int C, bool RELU>
__global__ void aggregate_kernel(const float* __restrict__ h,
                                 const float* __restrict__ bias,
                                 float* __restrict__ dest) {
    constexpr int F = H * C;
    constexpr int NV = F / 4;
    int gt = blockIdx.x * blockDim.x + threadIdx.x;
    int n = gt >> 4;
    int q = gt & 15;
    if (n >= NN) return;
    int hh = (H == 1) ? 0 : (q >> 2);

    const float ad = g_ad[n * H + hh];
    const int beg = __ldg(g_rowptr + n);
    const int end = __ldg(g_rowptr + n + 1);

    float4 acc = make_float4(0.f, 0.f, 0.f, 0.f);
    float den = 0.f;
    for (int i = beg; i < end; i++) {
        int s = __ldg(g_csr + i);
        float v = __ldg(g_as + s * H + hh) + ad;
        v = v > 0.f ? v : 0.2f * v;
        float w = __expf(v);
        den += w;
        if (q < NV) {
            float4 x = __ldg((const float4*)(h + (size_t)s * F) + q);
            acc.x += w * x.x;
            acc.y += w * x.y;
            acc.z += w * x.z;
            acc.w += w * x.w;
        }
    }
    if (q < NV) {
        float inv = 1.f / (den + 1e-16f);
        float4 b = __ldg((const float4*)bias + q);
        float4 o;
        o.x = acc.x * inv + b.x;
        o.y = acc.y * inv + b.y;
        o.z = acc.z * inv + b.z;
        o.w = acc.w * inv + b.w;
        if (RELU) {
            o.x = o.x > 0.f ? o.x : 0.f;
            o.y = o.y > 0.f ? o.y : 0.f;
            o.z = o.z > 0.f ? o.z : 0.f;
            o.w = o.w > 0.f ? o.w : 0.f;
        }
        *(float4*)(dest + (size_t)n * F + q * 4) = o;
    }
}

// ---------------- launch ----------------
extern "C" void kernel_launch(void* const* d_in, const int* in_sizes, int n_in,
                              void* d_out, int out_size) {
    const float* x = (const float*)d_in[0];
    const int* ei = (const int*)d_in[1];    // int32 (JAX x64 disabled)
    const float* W1 = (const float*)d_in[2];
    const float* asr1 = (const float*)d_in[3];
    const float* adr1 = (const float*)d_in[4];
    const float* b1 = (const float*)d_in[5];
    const float* W2 = (const float*)d_in[6];
    const float* asr2 = (const float*)d_in[7];
    const float* adr2 = (const float*)d_in[8];
    const float* b2 = (const float*)d_in[9];
    const float* W3 = (const float*)d_in[10];
    const float* asr3 = (const float*)d_in[11];
    const float* adr3 = (const float*)d_in[12];
    const float* b3 = (const float*)d_in[13];
    float* out = (float*)d_out;

    const int* esrc = ei;
    const int* edst = ei + EE;

    float *p_h, *p_feat;
    void* p_deg;
    cudaGetSymbolAddress((void**)&p_h, g_h);
    cudaGetSymbolAddress((void**)&p_feat, g_feat);
    cudaGetSymbolAddress(&p_deg, g_deg);

    constexpr int SMEM64 = (64 * (64 + 4) + 64 * 64) * 4;  // 33792
    constexpr int SMEM40 = (64 * (64 + 4) + 64 * 40) * 4;  // 27648

    const int gemmGrid = (NN + 63) / 64;   // 782
    const int edgeGrid = (ETOT + 255) / 256;
    const int aggGrid = (NN * 16 + 255) / 256;

    // Fork: CSR build on a side stream, overlapped with layer-1 GEMM.
    cudaStream_t s2;
    cudaStreamCreateWithFlags(&s2, cudaStreamNonBlocking);
    cudaEvent_t evFork, evJoin;
    cudaEventCreateWithFlags(&evFork, cudaEventDisableTiming);
    cudaEventCreateWithFlags(&evJoin, cudaEventDisableTiming);

    cudaEventRecord(evFork, 0);
    cudaStreamWaitEvent(s2, evFork, 0);
    cudaMemsetAsync(p_deg, 0, NN * sizeof(int), s2);
    hist_kernel<<<edgeGrid, 256, 0, s2>>>(edst);
    scan_kernel<<<1, 1024, 0, s2>>>();
    fill_kernel<<<edgeGrid, 256, 0, s2>>>(esrc, edst);
    cudaEventRecord(evJoin, s2);

    // ---------------- layer 1: 256 -> 4x16 ----------------
    gemm_kernel<256, 64, 64, true><<<gemmGrid, 256, SMEM64>>>(x, W1, p_h, asr1, adr1, NN);
    cudaStreamWaitEvent(0, evJoin, 0);   // CSR must be ready before aggregation
    aggregate_kernel<4, 16, true><<<aggGrid, 256>>>(p_h, b1, p_feat);

    // ---------------- layer 2: 64 -> 4x16 ----------------
    gemm_kernel<64, 64, 64, true><<<gemmGrid, 256, SMEM64>>>(p_feat, W2, p_h, asr2, adr2, NN);
    aggregate_kernel<4, 16, true><<<aggGrid, 256>>>(p_h, b2, p_feat);

    // ---------------- layer 3: 64 -> 1x40 ----------------
    gemm_kernel<64, 40, 64, false><<<gemmGrid, 160, SMEM40>>>(p_feat, W3, p_h, nullptr, nullptr, NN);
    prep_kernel<1, 40><<<(NN + 255) / 256, 256>>>(p_h, asr3, adr3);
    aggregate_kernel<1, 40, false><<<aggGrid, 256>>>(p_h, b3, out);
}